// round 7
// baseline (speedup 1.0000x reference)
#include <cuda_runtime.h>

#define Bn 4
#define Cn 64
#define Hn 128
#define Wn 128
#define HWn (Hn*Wn)

// ---------------- scratch (device globals; no runtime allocation) ----------------
__device__ __align__(16) float g_xT[Bn*HWn*Cn];       // x  in [B,H,W,C]
__device__ __align__(16) float g_interT[Bn*HWn*Cn];   // inter in [B,H,W,C]
__device__ __align__(16) float g_om[Bn*HWn*32];       // offsets+mask, pixel-major, padded to 32 ch
__device__ __align__(16) float g_woffT[1152*32];      // w_offset transposed: [r=cin*9+tap][o(pad32)]
__device__ __align__(16) float g_wdcnT[576*64];       // w_dcn transposed:    [r=c*9+k][o]
__device__ __align__(16) float g_wg1T[4096];          // [c][o]
__device__ __align__(16) float g_wg2T[4096];
__device__ __align__(16) float g_wb1T[4096];
__device__ __align__(16) float g_wb2T[4096];

// ---------------- weight prep ----------------
__global__ void prep_weights(const float* __restrict__ w_off,
                             const float* __restrict__ w_dcn,
                             const float* __restrict__ wg1, const float* __restrict__ wg2,
                             const float* __restrict__ wb1, const float* __restrict__ wb2) {
    int idx = blockIdx.x * blockDim.x + threadIdx.x;
    if (idx < 1152*32) {
        int r = idx >> 5, o = idx & 31;
        g_woffT[idx] = (o < 27) ? w_off[o*1152 + r] : 0.f;
    }
    if (idx < 576*64) {
        int r = idx >> 6, o = idx & 63;
        g_wdcnT[idx] = w_dcn[o*576 + r];
    }
    if (idx < 4096) {
        int c = idx >> 6, o = idx & 63;
        g_wg1T[idx] = wg1[o*64 + c];
        g_wg2T[idx] = wg2[o*64 + c];
        g_wb1T[idx] = wb1[o*64 + c];
        g_wb2T[idx] = wb2[o*64 + c];
    }
}

// ---------------- NCHW -> NHWC transpose (per batch: [64][16384] -> [16384][64]) ----
__global__ void transpose_k(const float* __restrict__ in, int which) {
    __shared__ float tile[32][33];
    float* out = which ? g_interT : g_xT;
    int b = blockIdx.z;
    int n0 = blockIdx.x * 32;    // pixel dim
    int c0 = blockIdx.y * 32;    // channel dim
    int tx = threadIdx.x, ty = threadIdx.y;
    const float* src = in + (size_t)b * Cn * HWn;
    float* dst = out + (size_t)b * HWn * Cn;
#pragma unroll
    for (int i = 0; i < 32; i += 8)
        tile[ty + i][tx] = src[(size_t)(c0 + ty + i) * HWn + n0 + tx];
    __syncthreads();
#pragma unroll
    for (int i = 0; i < 32; i += 8)
        dst[(size_t)(n0 + ty + i) * Cn + c0 + tx] = tile[tx][ty + i];
}

// ---------------- offset conv: om = conv3x3(concat(x,inter), w_off) + b; sigmoid on mask
// block: 256 thr = 8 o-groups(4 out each, 32 padded) x 32 pixels (one row segment)
__global__ __launch_bounds__(256) void offset_conv_k(
    const float* __restrict__ x, const float* __restrict__ inter,
    const float* __restrict__ b_off) {
    __shared__ float s_in[64 * 102];   // 64 ch x 3 rows x 34 cols = 26112 B
    int b = blockIdx.z, h = blockIdx.y, w0 = blockIdx.x * 32;
    int tid = threadIdx.x;
    int og = tid >> 5, p = tid & 31, o0 = og * 4;
    float acc0 = 0.f, acc1 = 0.f, acc2 = 0.f, acc3 = 0.f;

    for (int half = 0; half < 2; ++half) {
        const float* src = half ? inter : x;
        __syncthreads();
        for (int idx = tid; idx < 64 * 102; idx += 256) {
            int ci = idx / 102; int rem = idx - ci * 102;
            int ry = rem / 34;  int cx = rem - ry * 34;
            int y = h - 1 + ry, xw = w0 - 1 + cx;
            float v = 0.f;
            if ((unsigned)y < (unsigned)Hn && (unsigned)xw < (unsigned)Wn)
                v = src[((size_t)(b * Cn + ci) * Hn + y) * Wn + xw];
            s_in[idx] = v;
        }
        __syncthreads();
        const float* wb = g_woffT + half * 64 * 9 * 32 + o0;
        for (int ci = 0; ci < 64; ++ci) {
            const float* srow = s_in + ci * 102 + p;
            const float* wr = wb + ci * 288;
#pragma unroll
            for (int tap = 0; tap < 9; ++tap) {
                float4 w4 = *(const float4*)(wr + tap * 32);
                float s = srow[(tap / 3) * 34 + (tap % 3)];
                acc0 += w4.x * s; acc1 += w4.y * s;
                acc2 += w4.z * s; acc3 += w4.w * s;
            }
        }
    }

    float vals[4] = {acc0, acc1, acc2, acc3};
    float4 r;
    float* rv = (float*)&r;
#pragma unroll
    for (int j = 0; j < 4; ++j) {
        int o = o0 + j;
        float v = vals[j] + ((o < 27) ? b_off[o] : 0.f);
        if (o >= 18 && o < 27) v = 1.f / (1.f + expf(-v));   // sigmoid(mask)
        rv[j] = v;
    }
    size_t pix = ((size_t)b * Hn + h) * Wn + w0 + p;
    *(float4*)(g_om + pix * 32 + o0) = r;    // g_om 16B-aligned, pix*32+o0 % 4 == 0
}

__device__ __forceinline__ float lrelu(float v) { return v >= 0.f ? v : 0.1f * v; }

// ---------------- fused: gamma/beta chains + deformable sampling + DCN + residual ----
// block: 256 thr = 16 o-groups(4 out) x 16 pixels (row segment of 16)
__global__ __launch_bounds__(256) void fused_k(float* __restrict__ out) {
    __shared__ __align__(16) float s_samp[576 * 17]; // [r=c*9+k][p], pad 17 -> conflict-free
    __shared__ float s_om[16 * 27];
    // aliased into s_samp (dead before sampling phase writes it):
    float* s_iv = s_samp;                  // [16][65]
    float* s_t1 = s_samp + 1040;           // [16][66]
    float* s_t2 = s_samp + 1040 + 1056;    // [16][66]

    int b = blockIdx.z, h = blockIdx.y, w0 = blockIdx.x * 16;
    int tid = threadIdx.x;
    int og = tid >> 4, p = tid & 15, o0 = og * 4;
    size_t pixbase = ((size_t)b * Hn + h) * Wn + w0;

    // load om (27 per pixel) and inter vectors (64 per pixel)
    for (int idx = tid; idx < 16 * 27; idx += 256) {
        int pp = idx / 27, c = idx - pp * 27;
        s_om[idx] = g_om[(pixbase + pp) * 32 + c];
    }
    for (int idx = tid; idx < 16 * 64; idx += 256) {
        int pp = idx >> 6, c = idx & 63;
        s_iv[pp * 65 + c] = g_interT[(pixbase + pp) * 64 + c];
    }
    __syncthreads();

    // stage 1: t1 = lrelu(w_g1 @ iv), t2 = lrelu(w_b1 @ iv)
    float a10 = 0, a11 = 0, a12 = 0, a13 = 0;
    float a20 = 0, a21 = 0, a22 = 0, a23 = 0;
#pragma unroll 4
    for (int c = 0; c < 64; ++c) {
        float v = s_iv[p * 65 + c];
        float4 w1 = *(const float4*)(g_wg1T + c * 64 + o0);
        float4 w2 = *(const float4*)(g_wb1T + c * 64 + o0);
        a10 += w1.x * v; a11 += w1.y * v; a12 += w1.z * v; a13 += w1.w * v;
        a20 += w2.x * v; a21 += w2.y * v; a22 += w2.z * v; a23 += w2.w * v;
    }
    {
        // SCALAR stores: p*66 + o0 is not 16B-aligned for odd p (this was the
        // misaligned-address trap with float4 stores). Stride 66 is kept because
        // it makes the stage-2 scalar reads bank-conflict-free.
        float* t1p = s_t1 + p * 66 + o0;
        float* t2p = s_t2 + p * 66 + o0;
        t1p[0] = lrelu(a10); t1p[1] = lrelu(a11); t1p[2] = lrelu(a12); t1p[3] = lrelu(a13);
        t2p[0] = lrelu(a20); t2p[1] = lrelu(a21); t2p[2] = lrelu(a22); t2p[3] = lrelu(a23);
    }
    __syncthreads();

    // stage 2: gamma = w_g2 @ t1, beta = w_b2 @ t2 (kept in regs)
    float g0 = 0, g1 = 0, g2 = 0, g3 = 0;
    float e0 = 0, e1 = 0, e2 = 0, e3 = 0;
#pragma unroll 4
    for (int c = 0; c < 64; ++c) {
        float v1 = s_t1[p * 66 + c];
        float v2 = s_t2[p * 66 + c];
        float4 w1 = *(const float4*)(g_wg2T + c * 64 + o0);
        float4 w2 = *(const float4*)(g_wb2T + c * 64 + o0);
        g0 += w1.x * v1; g1 += w1.y * v1; g2 += w1.z * v1; g3 += w1.w * v1;
        e0 += w2.x * v2; e1 += w2.y * v2; e2 += w2.z * v2; e3 += w2.w * v2;
    }
    __syncthreads();   // all reads of aliased region done before sampling overwrites

    // sampling: fill s_samp[(c*9+k)*17 + p] = bilinear(x, p, k) * mask
    int wi = tid >> 5, lane = tid & 31;
    for (int task = wi; task < 144; task += 8) {
        int pp = task / 9, k = task - pp * 9;
        float dy = s_om[pp * 27 + k];
        float dx = s_om[pp * 27 + 9 + k];
        float m  = s_om[pp * 27 + 18 + k];
        int ky = k / 3, kx = k - ky * 3;
        float py = (float)(h + ky - 1) + dy;
        float px = (float)(w0 + pp + kx - 1) + dx;
        float fy = floorf(py), fx = floorf(px);
        float wy = py - fy, wx = px - fx;
        int y0 = (int)fy, x0 = (int)fx;
        bool vy0 = (unsigned)y0 < (unsigned)Hn;
        bool vy1 = (unsigned)(y0 + 1) < (unsigned)Hn;
        bool vx0 = (unsigned)x0 < (unsigned)Wn;
        bool vx1 = (unsigned)(x0 + 1) < (unsigned)Wn;
        float w00 = (1.f - wy) * (1.f - wx) * m;
        float w01 = (1.f - wy) * wx * m;
        float w10 = wy * (1.f - wx) * m;
        float w11 = wy * wx * m;
        const float* xb = g_xT + (size_t)b * HWn * Cn
                          + ((long long)y0 * Wn + x0) * Cn;
#pragma unroll
        for (int cc = 0; cc < 2; ++cc) {
            int c = lane + cc * 32;
            float v00 = (vy0 && vx0) ? xb[c] : 0.f;
            float v01 = (vy0 && vx1) ? xb[c + Cn] : 0.f;
            float v10 = (vy1 && vx0) ? xb[c + Wn * Cn] : 0.f;
            float v11 = (vy1 && vx1) ? xb[c + Wn * Cn + Cn] : 0.f;
            float val = v00 * w00 + v01 * w01 + v10 * w10 + v11 * w11;
            s_samp[(c * 9 + k) * 17 + pp] = val;
        }
    }
    __syncthreads();

    // DCN: d[o] = sum_r wdcnT[r][o] * samp[r][p]
    float d0 = 0, d1 = 0, d2 = 0, d3 = 0;
#pragma unroll 4
    for (int r = 0; r < 576; ++r) {
        float4 w4 = *(const float4*)(g_wdcnT + r * 64 + o0);
        float s = s_samp[r * 17 + p];
        d0 += w4.x * s; d1 += w4.y * s; d2 += w4.z * s; d3 += w4.w * s;
    }

    // epilogue: out = x + dcn + x*gamma + beta   (NCHW output)
    float4 xv = *(const float4*)(g_xT + (pixbase + p) * 64 + o0);
    float r0 = xv.x + d0 + xv.x * g0 + e0;
    float r1 = xv.y + d1 + xv.y * g1 + e1;
    float r2 = xv.z + d2 + xv.z * g2 + e2;
    float r3 = xv.w + d3 + xv.w * g3 + e3;
    size_t obase = ((size_t)(b * Cn + o0) * Hn + h) * Wn + w0 + p;
    out[obase]            = r0;
    out[obase + HWn]      = r1;
    out[obase + 2 * HWn]  = r2;
    out[obase + 3 * HWn]  = r3;
}

// ---------------- launch ----------------
extern "C" void kernel_launch(void* const* d_in, const int* in_sizes, int n_in,
                              void* d_out, int out_size) {
    const float* x     = (const float*)d_in[0];
    const float* inter = (const float*)d_in[1];
    const float* w_off = (const float*)d_in[2];
    const float* b_off = (const float*)d_in[3];
    const float* w_dcn = (const float*)d_in[4];
    const float* wg1   = (const float*)d_in[5];
    const float* wg2   = (const float*)d_in[6];
    const float* wb1   = (const float*)d_in[7];
    const float* wb2   = (const float*)d_in[8];
    float* out = (float*)d_out;

    prep_weights<<<144, 256>>>(w_off, w_dcn, wg1, wg2, wb1, wb2);
    transpose_k<<<dim3(HWn / 32, Cn / 32, Bn), dim3(32, 8)>>>(x, 0);
    transpose_k<<<dim3(HWn / 32, Cn / 32, Bn), dim3(32, 8)>>>(inter, 1);
    offset_conv_k<<<dim3(Wn / 32, Hn, Bn), 256>>>(x, inter, b_off);
    fused_k<<<dim3(Wn / 16, Hn, Bn), 256>>>(out);
}

// round 8
// speedup vs baseline: 1.0022x; 1.0022x over previous
#include <cuda_runtime.h>

#define Bn 4
#define Cn 64
#define Hn 128
#define Wn 128
#define HWn (Hn*Wn)

// ---------------- scratch (device globals; no runtime allocation) ----------------
__device__ __align__(16) float g_xT[Bn*HWn*Cn];       // x  in [B,H,W,C]
__device__ __align__(16) float g_interT[Bn*HWn*Cn];   // inter in [B,H,W,C]
__device__ __align__(16) float g_om[Bn*HWn*32];       // offsets+mask, pixel-major, padded to 32 ch
__device__ __align__(16) float g_woffT[1152*32];      // w_offset transposed: [r=cin*9+tap][o(pad32)]
__device__ __align__(16) float g_wdcnT[576*64];       // w_dcn transposed:    [r=c*9+k][o]
__device__ __align__(16) float g_wg1T[4096];          // [c][o]
__device__ __align__(16) float g_wg2T[4096];
__device__ __align__(16) float g_wb1T[4096];
__device__ __align__(16) float g_wb2T[4096];

// ---------------- weight prep ----------------
__global__ void prep_weights(const float* __restrict__ w_off,
                             const float* __restrict__ w_dcn,
                             const float* __restrict__ wg1, const float* __restrict__ wg2,
                             const float* __restrict__ wb1, const float* __restrict__ wb2) {
    int idx = blockIdx.x * blockDim.x + threadIdx.x;
    if (idx < 1152*32) {
        int r = idx >> 5, o = idx & 31;
        g_woffT[idx] = (o < 27) ? w_off[o*1152 + r] : 0.f;
    }
    if (idx < 576*64) {
        int r = idx >> 6, o = idx & 63;
        g_wdcnT[idx] = w_dcn[o*576 + r];
    }
    if (idx < 4096) {
        int c = idx >> 6, o = idx & 63;
        g_wg1T[idx] = wg1[o*64 + c];
        g_wg2T[idx] = wg2[o*64 + c];
        g_wb1T[idx] = wb1[o*64 + c];
        g_wb2T[idx] = wb2[o*64 + c];
    }
}

// ---------------- NCHW -> NHWC transpose (per batch: [64][16384] -> [16384][64]) ----
__global__ void transpose_k(const float* __restrict__ in, int which) {
    __shared__ float tile[32][33];
    float* out = which ? g_interT : g_xT;
    int b = blockIdx.z;
    int n0 = blockIdx.x * 32;    // pixel dim
    int c0 = blockIdx.y * 32;    // channel dim
    int tx = threadIdx.x, ty = threadIdx.y;
    const float* src = in + (size_t)b * Cn * HWn;
    float* dst = out + (size_t)b * HWn * Cn;
#pragma unroll
    for (int i = 0; i < 32; i += 8)
        tile[ty + i][tx] = src[(size_t)(c0 + ty + i) * HWn + n0 + tx];
    __syncthreads();
#pragma unroll
    for (int i = 0; i < 32; i += 8)
        dst[(size_t)(n0 + ty + i) * Cn + c0 + tx] = tile[tx][ty + i];
}

// ---------------- offset conv: om = conv3x3(concat(x,inter), w_off) + b; sigmoid on mask
// block: 256 thr = 8 o-groups(4 out each, 32 padded) x 32 pixels (one row segment)
__global__ __launch_bounds__(256) void offset_conv_k(
    const float* __restrict__ x, const float* __restrict__ inter,
    const float* __restrict__ b_off) {
    __shared__ float s_in[64 * 102];   // 64 ch x 3 rows x 34 cols = 26112 B
    int b = blockIdx.z, h = blockIdx.y, w0 = blockIdx.x * 32;
    int tid = threadIdx.x;
    int og = tid >> 5, p = tid & 31, o0 = og * 4;
    float acc0 = 0.f, acc1 = 0.f, acc2 = 0.f, acc3 = 0.f;

    for (int half = 0; half < 2; ++half) {
        const float* src = half ? inter : x;
        __syncthreads();
        for (int idx = tid; idx < 64 * 102; idx += 256) {
            int ci = idx / 102; int rem = idx - ci * 102;
            int ry = rem / 34;  int cx = rem - ry * 34;
            int y = h - 1 + ry, xw = w0 - 1 + cx;
            float v = 0.f;
            if ((unsigned)y < (unsigned)Hn && (unsigned)xw < (unsigned)Wn)
                v = src[((size_t)(b * Cn + ci) * Hn + y) * Wn + xw];
            s_in[idx] = v;
        }
        __syncthreads();
        const float* wb = g_woffT + half * 64 * 9 * 32 + o0;
        for (int ci = 0; ci < 64; ++ci) {
            const float* srow = s_in + ci * 102 + p;
            const float* wr = wb + ci * 288;
#pragma unroll
            for (int tap = 0; tap < 9; ++tap) {
                float4 w4 = *(const float4*)(wr + tap * 32);
                float s = srow[(tap / 3) * 34 + (tap % 3)];
                acc0 += w4.x * s; acc1 += w4.y * s;
                acc2 += w4.z * s; acc3 += w4.w * s;
            }
        }
    }

    float vals[4] = {acc0, acc1, acc2, acc3};
    float4 r;
    float* rv = (float*)&r;
#pragma unroll
    for (int j = 0; j < 4; ++j) {
        int o = o0 + j;
        float v = vals[j] + ((o < 27) ? b_off[o] : 0.f);
        if (o >= 18 && o < 27) v = 1.f / (1.f + expf(-v));   // sigmoid(mask)
        rv[j] = v;
    }
    size_t pix = ((size_t)b * Hn + h) * Wn + w0 + p;
    *(float4*)(g_om + pix * 32 + o0) = r;    // g_om 16B-aligned, pix*32+o0 % 4 == 0
}

__device__ __forceinline__ float lrelu(float v) { return v >= 0.f ? v : 0.1f * v; }

// ---------------- fused: gamma/beta chains + deformable sampling + DCN + residual ----
// block: 256 thr = 16 o-groups(4 out) x 16 pixels (row segment of 16)
__global__ __launch_bounds__(256) void fused_k(float* __restrict__ out) {
    __shared__ __align__(16) float s_samp[576 * 17]; // [r=c*9+k][p], pad 17 -> conflict-free
    __shared__ float s_om[16 * 27];
    // aliased into s_samp (dead before sampling phase writes it):
    float* s_iv = s_samp;                  // [16][65]
    float* s_t1 = s_samp + 1040;           // [16][66]
    float* s_t2 = s_samp + 1040 + 1056;    // [16][66]

    int b = blockIdx.z, h = blockIdx.y, w0 = blockIdx.x * 16;
    int tid = threadIdx.x;
    int og = tid >> 4, p = tid & 15, o0 = og * 4;
    size_t pixbase = ((size_t)b * Hn + h) * Wn + w0;

    // load om (27 per pixel) and inter vectors (64 per pixel)
    for (int idx = tid; idx < 16 * 27; idx += 256) {
        int pp = idx / 27, c = idx - pp * 27;
        s_om[idx] = g_om[(pixbase + pp) * 32 + c];
    }
    for (int idx = tid; idx < 16 * 64; idx += 256) {
        int pp = idx >> 6, c = idx & 63;
        s_iv[pp * 65 + c] = g_interT[(pixbase + pp) * 64 + c];
    }
    __syncthreads();

    // stage 1: t1 = lrelu(w_g1 @ iv), t2 = lrelu(w_b1 @ iv)
    float a10 = 0, a11 = 0, a12 = 0, a13 = 0;
    float a20 = 0, a21 = 0, a22 = 0, a23 = 0;
#pragma unroll 4
    for (int c = 0; c < 64; ++c) {
        float v = s_iv[p * 65 + c];
        float4 w1 = *(const float4*)(g_wg1T + c * 64 + o0);
        float4 w2 = *(const float4*)(g_wb1T + c * 64 + o0);
        a10 += w1.x * v; a11 += w1.y * v; a12 += w1.z * v; a13 += w1.w * v;
        a20 += w2.x * v; a21 += w2.y * v; a22 += w2.z * v; a23 += w2.w * v;
    }
    {
        // SCALAR stores: p*66 + o0 is not 16B-aligned for odd p (this was the
        // misaligned-address trap with float4 stores). Stride 66 is kept because
        // it makes the stage-2 scalar reads bank-conflict-free.
        float* t1p = s_t1 + p * 66 + o0;
        float* t2p = s_t2 + p * 66 + o0;
        t1p[0] = lrelu(a10); t1p[1] = lrelu(a11); t1p[2] = lrelu(a12); t1p[3] = lrelu(a13);
        t2p[0] = lrelu(a20); t2p[1] = lrelu(a21); t2p[2] = lrelu(a22); t2p[3] = lrelu(a23);
    }
    __syncthreads();

    // stage 2: gamma = w_g2 @ t1, beta = w_b2 @ t2 (kept in regs)
    float g0 = 0, g1 = 0, g2 = 0, g3 = 0;
    float e0 = 0, e1 = 0, e2 = 0, e3 = 0;
#pragma unroll 4
    for (int c = 0; c < 64; ++c) {
        float v1 = s_t1[p * 66 + c];
        float v2 = s_t2[p * 66 + c];
        float4 w1 = *(const float4*)(g_wg2T + c * 64 + o0);
        float4 w2 = *(const float4*)(g_wb2T + c * 64 + o0);
        g0 += w1.x * v1; g1 += w1.y * v1; g2 += w1.z * v1; g3 += w1.w * v1;
        e0 += w2.x * v2; e1 += w2.y * v2; e2 += w2.z * v2; e3 += w2.w * v2;
    }
    __syncthreads();   // all reads of aliased region done before sampling overwrites

    // sampling: fill s_samp[(c*9+k)*17 + p] = bilinear(x, p, k) * mask
    int wi = tid >> 5, lane = tid & 31;
    for (int task = wi; task < 144; task += 8) {
        int pp = task / 9, k = task - pp * 9;
        float dy = s_om[pp * 27 + k];
        float dx = s_om[pp * 27 + 9 + k];
        float m  = s_om[pp * 27 + 18 + k];
        int ky = k / 3, kx = k - ky * 3;
        float py = (float)(h + ky - 1) + dy;
        float px = (float)(w0 + pp + kx - 1) + dx;
        float fy = floorf(py), fx = floorf(px);
        float wy = py - fy, wx = px - fx;
        int y0 = (int)fy, x0 = (int)fx;
        bool vy0 = (unsigned)y0 < (unsigned)Hn;
        bool vy1 = (unsigned)(y0 + 1) < (unsigned)Hn;
        bool vx0 = (unsigned)x0 < (unsigned)Wn;
        bool vx1 = (unsigned)(x0 + 1) < (unsigned)Wn;
        float w00 = (1.f - wy) * (1.f - wx) * m;
        float w01 = (1.f - wy) * wx * m;
        float w10 = wy * (1.f - wx) * m;
        float w11 = wy * wx * m;
        const float* xb = g_xT + (size_t)b * HWn * Cn
                          + ((long long)y0 * Wn + x0) * Cn;
#pragma unroll
        for (int cc = 0; cc < 2; ++cc) {
            int c = lane + cc * 32;
            float v00 = (vy0 && vx0) ? xb[c] : 0.f;
            float v01 = (vy0 && vx1) ? xb[c + Cn] : 0.f;
            float v10 = (vy1 && vx0) ? xb[c + Wn * Cn] : 0.f;
            float v11 = (vy1 && vx1) ? xb[c + Wn * Cn + Cn] : 0.f;
            float val = v00 * w00 + v01 * w01 + v10 * w10 + v11 * w11;
            s_samp[(c * 9 + k) * 17 + pp] = val;
        }
    }
    __syncthreads();

    // DCN: d[o] = sum_r wdcnT[r][o] * samp[r][p]
    float d0 = 0, d1 = 0, d2 = 0, d3 = 0;
#pragma unroll 4
    for (int r = 0; r < 576; ++r) {
        float4 w4 = *(const float4*)(g_wdcnT + r * 64 + o0);
        float s = s_samp[r * 17 + p];
        d0 += w4.x * s; d1 += w4.y * s; d2 += w4.z * s; d3 += w4.w * s;
    }

    // epilogue: out = x + dcn + x*gamma + beta   (NCHW output)
    float4 xv = *(const float4*)(g_xT + (pixbase + p) * 64 + o0);
    float r0 = xv.x + d0 + xv.x * g0 + e0;
    float r1 = xv.y + d1 + xv.y * g1 + e1;
    float r2 = xv.z + d2 + xv.z * g2 + e2;
    float r3 = xv.w + d3 + xv.w * g3 + e3;
    size_t obase = ((size_t)(b * Cn + o0) * Hn + h) * Wn + w0 + p;
    out[obase]            = r0;
    out[obase + HWn]      = r1;
    out[obase + 2 * HWn]  = r2;
    out[obase + 3 * HWn]  = r3;
}

// ---------------- launch ----------------
extern "C" void kernel_launch(void* const* d_in, const int* in_sizes, int n_in,
                              void* d_out, int out_size) {
    const float* x     = (const float*)d_in[0];
    const float* inter = (const float*)d_in[1];
    const float* w_off = (const float*)d_in[2];
    const float* b_off = (const float*)d_in[3];
    const float* w_dcn = (const float*)d_in[4];
    const float* wg1   = (const float*)d_in[5];
    const float* wg2   = (const float*)d_in[6];
    const float* wb1   = (const float*)d_in[7];
    const float* wb2   = (const float*)d_in[8];
    float* out = (float*)d_out;

    prep_weights<<<144, 256>>>(w_off, w_dcn, wg1, wg2, wb1, wb2);
    transpose_k<<<dim3(HWn / 32, Cn / 32, Bn), dim3(32, 8)>>>(x, 0);
    transpose_k<<<dim3(HWn / 32, Cn / 32, Bn), dim3(32, 8)>>>(inter, 1);
    offset_conv_k<<<dim3(Wn / 32, Hn, Bn), 256>>>(x, inter, b_off);
    fused_k<<<dim3(Wn / 16, Hn, Bn), 256>>>(out);
}